// round 4
// baseline (speedup 1.0000x reference)
#include <cuda_runtime.h>
#include <cstdint>

// MeshConv: g = 5 symmetric features of x[...,0:5]; y = conv1x5(g, W) + b
// x: (4,16,500000,5) f32   W: (16,16,1,5) f32   b: (16,)   y: (4,16,5,499996) f32

#define F_DIM  500000
#define FO     499996
#define CI_N   16
#define CO_N   16
#define N_B    4
#define TILE   128
#define GROWS  132            // TILE + 4 halo rows
#define NTHR   320            // 5h * 64 (8cog * 8fg)
#define WSTR   6              // padded ull stride per (ci,co): 48B, 16B-aligned

typedef unsigned long long ull;

__device__ __forceinline__ void fma2(ull &d, ull a, ull b) {
    asm("fma.rn.f32x2 %0, %1, %2, %0;" : "+l"(d) : "l"(a), "l"(b));
}
__device__ __forceinline__ ull pack2(float lo, float hi) {
    ull r; asm("mov.b64 %0, {%1, %2};" : "=l"(r) : "f"(lo), "f"(hi)); return r;
}
__device__ __forceinline__ float2 unpack2(ull v) {
    float2 r; asm("mov.b64 {%0, %1}, %2;" : "=f"(r.x), "=f"(r.y) : "l"(v)); return r;
}
// LDS.128 delivering two aligned f32 pairs directly (no pack MOVs)
__device__ __forceinline__ void lds128(ull &a, ull &b, uint32_t addr) {
    asm("ld.shared.v2.u64 {%0, %1}, [%2];" : "=l"(a), "=l"(b) : "r"(addr));
}
__device__ __forceinline__ ull lds64(uint32_t addr) {
    ull a; asm("ld.shared.u64 %0, [%1];" : "=l"(a) : "r"(addr)); return a;
}

// smem: g 16ci*5h*132 f32 = 42240B | W 16ci*16co*6 ull = 12288B | b 64B
#define G_FLOATS (CI_N*5*GROWS)
#define SMEM_BYTES (G_FLOATS*4 + CI_N*CO_N*WSTR*8 + 64)

extern __shared__ float smem_dyn[];

__global__ __launch_bounds__(NTHR, 2)
void meshconv_kernel(const float* __restrict__ x, const float* __restrict__ W,
                     const float* __restrict__ b, float* __restrict__ y)
{
    float* gsh  = smem_dyn;                         // [ci][h][row]
    ull*   wdsh = (ull*)(smem_dyn + G_FLOATS);      // [ci][co][k(+pad)] {w,w} pairs
    float* bsh  = (float*)(wdsh + CI_N*CO_N*WSTR);  // [co]

    const int tid = threadIdx.x;
    const int n   = blockIdx.y;
    const int f0  = blockIdx.x * TILE;

    // ---- preload W (duplicated {w,w} pairs, padded stride) + bias ----
    for (int idx = tid; idx < CO_N*CI_N*5; idx += NTHR) {
        int co = idx / (CI_N*5);
        int r  = idx % (CI_N*5);
        int ci = r / 5, k = r % 5;
        float w = W[idx];
        wdsh[(ci*CO_N + co)*WSTR + k] = pack2(w, w);
    }
    if (tid < CO_N) bsh[tid] = b[tid];

    // ---- build g tile in smem (x read exactly once from DRAM) ----
    for (int id = tid; id < CI_N*GROWS; id += NTHR) {
        int ci  = id / GROWS;
        int row = id % GROWS;
        int f   = f0 + row;
        float v0 = 0.f, v1 = 0.f, v2 = 0.f, v3 = 0.f, v4 = 0.f;
        if (f < F_DIM) {
            const float* xp = x + ((size_t)(n*CI_N + ci)*F_DIM + f)*5;
            v0 = xp[0]; v1 = xp[1]; v2 = xp[2]; v3 = xp[3]; v4 = xp[4];
        }
        float* gp = gsh + ci*5*GROWS;
        gp[0*GROWS + row] = v0;
        gp[1*GROWS + row] = v1 + v3;
        gp[2*GROWS + row] = v2 + v4;
        gp[3*GROWS + row] = fabsf(v1 - v3);
        gp[4*GROWS + row] = fabsf(v2 - v4);
    }
    __syncthreads();

    // ---- compute mapping: 5h x (8cog x 8fg); thread = 2co x 2spans x 4 pairs ----
    const int h   = tid >> 6;        // 0..4 (uniform per warp)
    const int t64 = tid & 63;
    const int cog = t64 >> 3;        // 0..7
    const int fg  = t64 & 7;         // 0..7
    const int co0 = cog * 2;

    const uint32_t g_base = (uint32_t)__cvta_generic_to_shared(gsh + h*GROWS);
    const uint32_t w_base = (uint32_t)__cvta_generic_to_shared(wdsh + co0*WSTR);

    const float bv0 = bsh[co0], bv1 = bsh[co0+1];
    const ull biasp[2] = { pack2(bv0, bv0), pack2(bv1, bv1) };

    #pragma unroll
    for (int span = 0; span < 2; ++span) {
        const int fbase = span*64 + fg*8;      // 8 consecutive outputs

        ull A[2][4], B[2][5];
        #pragma unroll
        for (int c = 0; c < 2; ++c) {
            #pragma unroll
            for (int m = 0; m < 4; ++m) A[c][m] = biasp[c];
            #pragma unroll
            for (int m = 0; m < 5; ++m) B[c][m] = 0ULL;
        }

        uint32_t gaddr = g_base + fbase*4;
        uint32_t waddr = w_base;

        #pragma unroll 1
        for (int ci = 0; ci < CI_N; ++ci) {
            ull P0, P1, P2, P3, P4, P5;        // aligned pairs g[fb+2i..fb+2i+1]
            lds128(P0, P1, gaddr);
            lds128(P2, P3, gaddr + 16);
            lds128(P4, P5, gaddr + 32);

            #pragma unroll
            for (int c = 0; c < 2; ++c) {
                ull w0, w1, w2, w3, w4;
                uint32_t wa = waddr + c*(WSTR*8);
                lds128(w0, w1, wa);
                lds128(w2, w3, wa + 16);
                w4 = lds64(wa + 32);

                // even taps (k=0,2,4): aligned, land directly on output pairs
                fma2(A[c][0], P0, w0); fma2(A[c][0], P1, w2); fma2(A[c][0], P2, w4);
                fma2(A[c][1], P1, w0); fma2(A[c][1], P2, w2); fma2(A[c][1], P3, w4);
                fma2(A[c][2], P2, w0); fma2(A[c][2], P3, w2); fma2(A[c][2], P4, w4);
                fma2(A[c][3], P3, w0); fma2(A[c][3], P4, w2); fma2(A[c][3], P5, w4);
                // odd taps (k=1,3): aligned pairs, shifted semantics resolved in epilogue
                fma2(B[c][0], P0, w1); fma2(B[c][0], P1, w3);
                fma2(B[c][1], P1, w1); fma2(B[c][1], P2, w3);
                fma2(B[c][2], P2, w1); fma2(B[c][2], P3, w3);
                fma2(B[c][3], P3, w1); fma2(B[c][3], P4, w3);
                fma2(B[c][4], P4, w1); fma2(B[c][4], P5, w3);
            }
            gaddr += 5*GROWS*4;        // next ci in g
            waddr += CO_N*WSTR*8;      // next ci in W
        }

        // ---- combine A/B and store (epilogue-only packing) ----
        #pragma unroll
        for (int c = 0; c < 2; ++c) {
            const int f = f0 + fbase;
            float* yp = y + ((size_t)((n*CO_N + co0 + c)*5 + h))*FO + f;

            float2 Bv[5];
            #pragma unroll
            for (int m = 0; m < 5; ++m) Bv[m] = unpack2(B[c][m]);

            float o[8];
            #pragma unroll
            for (int m = 0; m < 4; ++m) {
                float2 a = unpack2(A[c][m]);
                o[2*m]   = a.x + Bv[m].y;      // y[f+2m]   = A.lo + B[m].hi
                o[2*m+1] = a.y + Bv[m+1].x;    // y[f+2m+1] = A.hi + B[m+1].lo
            }
            // f,FO both ≡ 0 (mod 4) → f<FO implies whole quad in range
            if (f < FO)
                *(float4*)(yp)     = make_float4(o[0], o[1], o[2], o[3]);
            if (f + 4 < FO)
                *(float4*)(yp + 4) = make_float4(o[4], o[5], o[6], o[7]);
        }
    }
}

extern "C" void kernel_launch(void* const* d_in, const int* in_sizes, int n_in,
                              void* d_out, int out_size)
{
    (void)in_sizes; (void)n_in; (void)out_size;
    const float* x = (const float*)d_in[0];
    const float* W = (const float*)d_in[1];
    const float* b = (const float*)d_in[2];
    float*       y = (float*)d_out;

    cudaFuncSetAttribute(meshconv_kernel,
                         cudaFuncAttributeMaxDynamicSharedMemorySize, SMEM_BYTES);

    dim3 grid((FO + TILE - 1) / TILE, N_B);
    meshconv_kernel<<<grid, NTHR, SMEM_BYTES>>>(x, W, b, y);
}

// round 5
// speedup vs baseline: 1.6715x; 1.6715x over previous
#include <cuda_runtime.h>
#include <cstdint>

// MeshConv: g = 5 symmetric features of x[...,0:5]; y = conv1x5(g, W) + b
// x: (4,16,500000,5) f32   W: (16,16,1,5) f32   b: (16,)   y: (4,16,5,499996) f32
//
// Scheme: g duplicated in smem as even array e[j]=g[j] and shifted array o[j]=g[j+1].
// Every conv tap then hits an ALIGNED f32 pair -> pure fma.rn.f32x2, zero pack MOVs,
// zero accumulator overhead (5 fma2 per output-pair per ci per co).

#define F_DIM  500000
#define FO     499996
#define CI_N   16
#define CO_N   16
#define N_B    4
#define TILE   64
#define GR     68             // TILE + 4 halo rows
#define NPAIR  34             // ull pairs per (ci,h) row in each of e/o
#define NTHR   160            // 5h * 4cog * 8fg
#define WSTR   6              // padded ull stride per (ci,co): 48B (16B-aligned)

typedef unsigned long long ull;

__device__ __forceinline__ void fma2(ull &d, ull a, ull b) {
    asm("fma.rn.f32x2 %0, %1, %2, %0;" : "+l"(d) : "l"(a), "l"(b));
}
__device__ __forceinline__ ull pack2(float lo, float hi) {
    ull r; asm("mov.b64 %0, {%1, %2};" : "=l"(r) : "f"(lo), "f"(hi)); return r;
}
__device__ __forceinline__ float2 unpack2(ull v) {
    float2 r; asm("mov.b64 {%0, %1}, %2;" : "=f"(r.x), "=f"(r.y) : "l"(v)); return r;
}
__device__ __forceinline__ void lds128(ull &a, ull &b, uint32_t addr) {
    asm("ld.shared.v2.u64 {%0, %1}, [%2];" : "=l"(a), "=l"(b) : "r"(addr));
}
__device__ __forceinline__ ull lds64(uint32_t addr) {
    ull a; asm("ld.shared.u64 %0, [%1];" : "=l"(a) : "r"(addr)); return a;
}

// smem (ull units):
//   e : [ci][h][NPAIR]  = 16*5*34 = 2720 ull  (21760 B)
//   o : [ci][h][NPAIR]  = 2720 ull            (21760 B)
//   w : [ci][co][WSTR]  = 16*16*6 = 1536 ull  (12288 B)  {w,w} duplicated pairs
//   b : 16 floats (8 ull)
#define E_ULL   (CI_N*5*NPAIR)
#define W_ULL   (CI_N*CO_N*WSTR)
#define SMEM_BYTES ((E_ULL*2 + W_ULL + 8) * 8)

extern __shared__ ull smem_dyn[];

__global__ __launch_bounds__(NTHR, 4)
void meshconv_kernel(const float* __restrict__ x, const float* __restrict__ W,
                     const float* __restrict__ b, float* __restrict__ y)
{
    ull*   esh  = smem_dyn;                 // even pairs
    ull*   osh  = smem_dyn + E_ULL;         // odd (shifted) pairs
    ull*   wdsh = smem_dyn + 2*E_ULL;       // weights {w,w}
    float* bsh  = (float*)(wdsh + W_ULL);   // bias

    const int tid = threadIdx.x;
    const int n   = blockIdx.y;
    const int f0  = blockIdx.x * TILE;

    // ---- preload W (duplicated {w,w}, padded stride) + bias ----
    for (int idx = tid; idx < CO_N*CI_N*5; idx += NTHR) {
        int co = idx / (CI_N*5);
        int r  = idx % (CI_N*5);
        int ci = r / 5, k = r % 5;
        float w = W[idx];
        wdsh[(ci*CO_N + co)*WSTR + k] = pack2(w, w);
    }
    if (tid < CO_N) bsh[tid] = b[tid];

    // ---- build g tile: e[r] = g[r], o[r-1] = g[r] (shifted copy) ----
    for (int id = tid; id < CI_N*GR; id += NTHR) {
        int ci = id / GR;
        int r  = id % GR;
        int f  = f0 + r;
        float v0 = 0.f, v1 = 0.f, v2 = 0.f, v3 = 0.f, v4 = 0.f;
        if (f < F_DIM) {
            const float* xp = x + ((size_t)(n*CI_N + ci)*F_DIM + f)*5;
            v0 = xp[0]; v1 = xp[1]; v2 = xp[2]; v3 = xp[3]; v4 = xp[4];
        }
        float g0 = v0;
        float g1 = v1 + v3;
        float g2 = v2 + v4;
        float g3 = fabsf(v1 - v3);
        float g4 = fabsf(v2 - v4);

        float* ef = (float*)(esh + (size_t)ci*5*NPAIR);   // [h][2*NPAIR] floats
        float* of = (float*)(osh + (size_t)ci*5*NPAIR);
        ef[0*GR + r] = g0;  ef[1*GR + r] = g1;  ef[2*GR + r] = g2;
        ef[3*GR + r] = g3;  ef[4*GR + r] = g4;
        if (r >= 1) {
            of[0*GR + r-1] = g0;  of[1*GR + r-1] = g1;  of[2*GR + r-1] = g2;
            of[3*GR + r-1] = g3;  of[4*GR + r-1] = g4;
        }
    }
    __syncthreads();

    // ---- compute: thread = (h, 4-co group, f-group of 8 floats = 4 pairs) ----
    const int h    = tid >> 5;       // 0..4 (warp-uniform)
    const int lane = tid & 31;
    const int cog  = lane >> 3;      // 0..3
    const int fg   = lane & 7;       // 0..7
    const int co0  = cog * 4;

    uint32_t eaddr = (uint32_t)__cvta_generic_to_shared(esh + h*NPAIR + fg*4);
    uint32_t oaddr = (uint32_t)__cvta_generic_to_shared(osh + h*NPAIR + fg*4);
    uint32_t waddr = (uint32_t)__cvta_generic_to_shared(wdsh + co0*WSTR);

    ull acc[4][4];
    #pragma unroll
    for (int c = 0; c < 4; ++c) {
        float bb = bsh[co0 + c];
        ull bp = pack2(bb, bb);
        #pragma unroll
        for (int m = 0; m < 4; ++m) acc[c][m] = bp;
    }

    #pragma unroll 1
    for (int ci = 0; ci < CI_N; ++ci) {
        ull P0, P1, P2, P3, P4, P5;      // e pairs i..i+5
        ull Q0, Q1, Q2, Q3, Q4;          // o pairs i..i+4
        lds128(P0, P1, eaddr);
        lds128(P2, P3, eaddr + 16);
        lds128(P4, P5, eaddr + 32);
        lds128(Q0, Q1, oaddr);
        lds128(Q2, Q3, oaddr + 16);
        Q4 = lds64(oaddr + 32);

        #pragma unroll
        for (int c = 0; c < 4; ++c) {
            ull w0, w1, w2, w3, w4;
            uint32_t wa = waddr + c*(WSTR*8);
            lds128(w0, w1, wa);
            lds128(w2, w3, wa + 16);
            w4 = lds64(wa + 32);

            fma2(acc[c][0], P0, w0); fma2(acc[c][1], P1, w0);
            fma2(acc[c][2], P2, w0); fma2(acc[c][3], P3, w0);
            fma2(acc[c][0], Q0, w1); fma2(acc[c][1], Q1, w1);
            fma2(acc[c][2], Q2, w1); fma2(acc[c][3], Q3, w1);
            fma2(acc[c][0], P1, w2); fma2(acc[c][1], P2, w2);
            fma2(acc[c][2], P3, w2); fma2(acc[c][3], P4, w2);
            fma2(acc[c][0], Q1, w3); fma2(acc[c][1], Q2, w3);
            fma2(acc[c][2], Q3, w3); fma2(acc[c][3], Q4, w3);
            fma2(acc[c][0], P2, w4); fma2(acc[c][1], P3, w4);
            fma2(acc[c][2], P4, w4); fma2(acc[c][3], P5, w4);
        }
        eaddr += 5*NPAIR*8;              // next ci
        oaddr += 5*NPAIR*8;
        waddr += CO_N*WSTR*8;
    }

    // ---- store: 8 consecutive floats per co (two float4) ----
    const int f = f0 + fg*8;
    #pragma unroll
    for (int c = 0; c < 4; ++c) {
        float* yp = y + ((size_t)((n*CO_N + co0 + c)*5 + h))*FO + f;
        float2 a0 = unpack2(acc[c][0]);
        float2 a1 = unpack2(acc[c][1]);
        float2 a2 = unpack2(acc[c][2]);
        float2 a3 = unpack2(acc[c][3]);
        if (f < FO)                      // FO%4==0, f%4==0 -> whole quad in range
            *(float4*)(yp)     = make_float4(a0.x, a0.y, a1.x, a1.y);
        if (f + 4 < FO)
            *(float4*)(yp + 4) = make_float4(a2.x, a2.y, a3.x, a3.y);
    }
}

extern "C" void kernel_launch(void* const* d_in, const int* in_sizes, int n_in,
                              void* d_out, int out_size)
{
    (void)in_sizes; (void)n_in; (void)out_size;
    const float* x = (const float*)d_in[0];
    const float* W = (const float*)d_in[1];
    const float* b = (const float*)d_in[2];
    float*       y = (float*)d_out;

    cudaFuncSetAttribute(meshconv_kernel,
                         cudaFuncAttributeMaxDynamicSharedMemorySize, SMEM_BYTES);

    dim3 grid((FO + TILE - 1) / TILE, N_B);
    meshconv_kernel<<<grid, NTHR, SMEM_BYTES>>>(x, W, b, y);
}

// round 6
// speedup vs baseline: 1.8087x; 1.0821x over previous
#include <cuda_runtime.h>
#include <cstdint>

// MeshConv: g = 5 symmetric features of x[...,0:5]; y = conv1x5(g, W) + b
// x: (4,16,500000,5) f32   W: (16,16,1,5) f32   b: (16,)   y: (4,16,5,499996) f32
//
// f32x2 lanes packed over (co, co+1): acc = {y(c,f), y(c+1,f)}.
//  - W operand {w_k(c), w_k(c+1)} is non-redundant (1.0 B/fma2, amortized over 8 f)
//  - g operand {g,g} built by register dup from scalar smem loads (0.3 B/fma2)
//  - no shifted g duplicate needed -> half the smem, half the build stores

#define F_DIM  500000
#define FO     499996
#define CI_N   16
#define CO_N   16
#define N_B    4
#define TILE   128
#define GR     132            // TILE + 4 halo
#define NTHR   160            // 5h * 2cog * 16fg

typedef unsigned long long ull;

__device__ __forceinline__ void fma2(ull &d, ull a, ull b) {
    asm("fma.rn.f32x2 %0, %1, %2, %0;" : "+l"(d) : "l"(a), "l"(b));
}
__device__ __forceinline__ ull pack2(float lo, float hi) {
    ull r; asm("mov.b64 %0, {%1, %2};" : "=l"(r) : "f"(lo), "f"(hi)); return r;
}
__device__ __forceinline__ float2 unpack2(ull v) {
    float2 r; asm("mov.b64 {%0, %1}, %2;" : "=f"(r.x), "=f"(r.y) : "l"(v)); return r;
}
__device__ __forceinline__ void lds128u(ull &a, ull &b, uint32_t addr) {
    asm("ld.shared.v2.u64 {%0, %1}, [%2];" : "=l"(a), "=l"(b) : "r"(addr));
}
__device__ __forceinline__ float4 lds128f(uint32_t addr) {
    float4 v;
    asm("ld.shared.v4.f32 {%0, %1, %2, %3}, [%4];"
        : "=f"(v.x), "=f"(v.y), "=f"(v.z), "=f"(v.w) : "r"(addr));
    return v;
}

// smem: g [ci][h][GR] floats = 16*5*132*4 = 42240B ; W [ci][cog][k][j] ull = 640*8 = 5120B
#define G_FLOATS (CI_N*5*GR)
#define W_ULL    (CI_N*2*5*4)
#define SMEM_BYTES (G_FLOATS*4 + W_ULL*8)

extern __shared__ float smem_dyn[];

__global__ __launch_bounds__(NTHR, 3)
void meshconv_kernel(const float* __restrict__ x, const float* __restrict__ W,
                     const float* __restrict__ b, float* __restrict__ y)
{
    float* gsh  = smem_dyn;
    ull*   wdsh = (ull*)(smem_dyn + G_FLOATS);

    const int tid = threadIdx.x;
    const int n   = blockIdx.y;
    const int f0  = blockIdx.x * TILE;

    // ---- pack W into smem: wdsh[((ci*2+cg)*5+k)*4+j] = {W(c0), W(c0+1)}, c0=cg*8+2j ----
    for (int idx = tid; idx < W_ULL; idx += NTHR) {
        int j  = idx & 3;
        int t  = idx >> 2;
        int k  = t % 5;
        int u  = t / 5;
        int cg = u & 1;
        int ci = u >> 1;
        int c0 = cg*8 + 2*j;
        wdsh[idx] = pack2(W[(c0*CI_N + ci)*5 + k], W[((c0+1)*CI_N + ci)*5 + k]);
    }

    // ---- build g tile (single array, scalar floats) ----
    for (int id = tid; id < CI_N*GR; id += NTHR) {
        int ci = id / GR;
        int r  = id % GR;
        int f  = f0 + r;
        float v0 = 0.f, v1 = 0.f, v2 = 0.f, v3 = 0.f, v4 = 0.f;
        if (f < F_DIM) {
            const float* xp = x + ((size_t)(n*CI_N + ci)*F_DIM + f)*5;
            v0 = xp[0]; v1 = xp[1]; v2 = xp[2]; v3 = xp[3]; v4 = xp[4];
        }
        float* gp = gsh + ci*5*GR;
        gp[0*GR + r] = v0;
        gp[1*GR + r] = v1 + v3;
        gp[2*GR + r] = v2 + v4;
        gp[3*GR + r] = fabsf(v1 - v3);
        gp[4*GR + r] = fabsf(v2 - v4);
    }
    __syncthreads();

    // ---- compute: thread = (h, cog, fg): 8 consecutive f x 8 co (4 co-pairs) ----
    const int h    = tid >> 5;        // warp-uniform (5 warps)
    const int lane = tid & 31;
    const int cg   = lane >> 4;       // 0..1
    const int fg   = lane & 15;       // 0..15
    const int co0  = cg * 8;

    uint32_t gaddr = (uint32_t)__cvta_generic_to_shared(gsh + h*GR + fg*8);
    uint32_t waddr = (uint32_t)__cvta_generic_to_shared(wdsh + cg*20);

    ull acc[8][4];
    #pragma unroll
    for (int j = 0; j < 4; ++j) {
        ull bp = pack2(b[co0 + 2*j], b[co0 + 2*j + 1]);
        #pragma unroll
        for (int p = 0; p < 8; ++p) acc[p][j] = bp;
    }

    #pragma unroll 1
    for (int ci = 0; ci < CI_N; ++ci) {
        float4 va = lds128f(gaddr);
        float4 vb = lds128f(gaddr + 16);
        float4 vc = lds128f(gaddr + 32);
        ull gd[12];
        gd[0]  = pack2(va.x, va.x);  gd[1]  = pack2(va.y, va.y);
        gd[2]  = pack2(va.z, va.z);  gd[3]  = pack2(va.w, va.w);
        gd[4]  = pack2(vb.x, vb.x);  gd[5]  = pack2(vb.y, vb.y);
        gd[6]  = pack2(vb.z, vb.z);  gd[7]  = pack2(vb.w, vb.w);
        gd[8]  = pack2(vc.x, vc.x);  gd[9]  = pack2(vc.y, vc.y);
        gd[10] = pack2(vc.z, vc.z);  gd[11] = pack2(vc.w, vc.w);

        #pragma unroll
        for (int k = 0; k < 5; ++k) {
            ull w0, w1, w2, w3;                        // 4 co-pairs for tap k
            lds128u(w0, w1, waddr + k*32);
            lds128u(w2, w3, waddr + k*32 + 16);
            #pragma unroll
            for (int p = 0; p < 8; ++p) {
                fma2(acc[p][0], gd[p+k], w0);
                fma2(acc[p][1], gd[p+k], w1);
                fma2(acc[p][2], gd[p+k], w2);
                fma2(acc[p][3], gd[p+k], w3);
            }
        }
        gaddr += 5*GR*4;       // next ci in g
        waddr += 40*8;         // next ci in W (40 ull)
    }

    // ---- store: per co-pair, unpack to per-co float4 runs (coalesced) ----
    const int f = f0 + fg*8;
    #pragma unroll
    for (int j = 0; j < 4; ++j) {
        const int c = co0 + 2*j;
        float* ylo = y + ((size_t)((n*CO_N + c)*5 + h))*FO + f;
        float* yhi = ylo + (size_t)5*FO;               // co+1 row

        float2 a0 = unpack2(acc[0][j]), a1 = unpack2(acc[1][j]);
        float2 a2 = unpack2(acc[2][j]), a3 = unpack2(acc[3][j]);
        float2 a4 = unpack2(acc[4][j]), a5 = unpack2(acc[5][j]);
        float2 a6 = unpack2(acc[6][j]), a7 = unpack2(acc[7][j]);

        if (f < FO) {                                  // FO%4==0, f%8==0 -> quad safe
            *(float4*)ylo = make_float4(a0.x, a1.x, a2.x, a3.x);
            *(float4*)yhi = make_float4(a0.y, a1.y, a2.y, a3.y);
        }
        if (f + 4 < FO) {
            *(float4*)(ylo + 4) = make_float4(a4.x, a5.x, a6.x, a7.x);
            *(float4*)(yhi + 4) = make_float4(a4.y, a5.y, a6.y, a7.y);
        }
    }
}

extern "C" void kernel_launch(void* const* d_in, const int* in_sizes, int n_in,
                              void* d_out, int out_size)
{
    (void)in_sizes; (void)n_in; (void)out_size;
    const float* x = (const float*)d_in[0];
    const float* W = (const float*)d_in[1];
    const float* b = (const float*)d_in[2];
    float*       y = (float*)d_out;

    cudaFuncSetAttribute(meshconv_kernel,
                         cudaFuncAttributeMaxDynamicSharedMemorySize, SMEM_BYTES);

    dim3 grid((FO + TILE - 1) / TILE, N_B);
    meshconv_kernel<<<grid, NTHR, SMEM_BYTES>>>(x, W, b, y);
}